// round 15
// baseline (speedup 1.0000x reference)
#include <cuda_runtime.h>
#include <mma.h>
#include <cstdint>

using namespace nvcuda;

// Problem constants
#define CB 8
#define CS 1024
#define CD 1024
#define CH 16
#define CHD 64
#define CL 512
#define CLHD 32
#define MROWS (CB*CS)   // 8192
#define M_ALPHA (-1000000000.0f)
#define NSPLIT 8        // split-K factor for the compose GEMM

// ---------------------------------------------------------------------------
// Scratch (static device globals — no runtime allocation allowed)
// ---------------------------------------------------------------------------
__device__ float g_Wcat[(size_t)CD*CD];     // [Wql | w_ckv] tf32-rounded   4MB
__device__ float g_bcat[CD];                // [bql | 0]
__device__ float g_qc[(size_t)MROWS*CD];    // [q_latent | combined] (tf32) 32MB
__device__ float g_v[(size_t)MROWS*CD];     // v (tf32-rounded)             32MB
__device__ float g_z[(size_t)MROWS*CD];     // attention output (tf32)      32MB
__device__ float g_xr[(size_t)MROWS*CD];    // x tf32-rounded               32MB
__device__ float g_wuvr[(size_t)CL*CD];     // wuv tf32-rounded             2MB
__device__ float g_wor[(size_t)CD*CD];      // wo tf32-rounded              4MB
__device__ float g_part[(size_t)NSPLIT*CD*CL]; // compose split-K partials  16MB

__device__ __forceinline__ uint32_t smem_u32(const void* p) {
    return (uint32_t)__cvta_generic_to_shared(p);
}
__device__ __forceinline__ float tf32r(float x) {
    uint32_t u;
    asm("cvt.rna.tf32.f32 %0, %1;" : "=r"(u) : "f"(x));
    return __uint_as_float(u);
}
#define CPA(dst, src) asm volatile("cp.async.cg.shared.global [%0], [%1], 16;\n" :: "r"(dst), "l"(src))
#define CPCOMMIT()    asm volatile("cp.async.commit_group;\n")
#define CPWAIT0()     asm volatile("cp.async.wait_group 0;\n")

#define MMA_TF32(d, a0,a1,a2,a3, b0,b1) \
    asm volatile("mma.sync.aligned.m16n8k8.row.col.f32.tf32.tf32.f32 " \
        "{%0,%1,%2,%3}, {%4,%5,%6,%7}, {%8,%9}, {%0,%1,%2,%3};" \
        : "+f"(d[0]),"+f"(d[1]),"+f"(d[2]),"+f"(d[3]) \
        : "r"(a0),"r"(a1),"r"(a2),"r"(a3), "r"(b0),"r"(b1))

// Round-copy: dst = rna_tf32(src), float4-vectorized. n4 = count of float4s.
__global__ void round_copy_kernel(const float* __restrict__ src,
                                  float* __restrict__ dst, int n4)
{
    int i = blockIdx.x * 256 + threadIdx.x;
    if (i < n4) {
        float4 v = *(const float4*)(src + (size_t)i * 4);
        v.x = tf32r(v.x); v.y = tf32r(v.y); v.z = tf32r(v.z); v.w = tf32r(v.w);
        *(float4*)(dst + (size_t)i * 4) = v;
    }
}

// ---------------------------------------------------------------------------
// Pipelined GEMM: C(M,N) = A(M,K) @ B(K,N) (+ bias[col]), row-major, explicit
// leading dims. Operands must be PRE-ROUNDED to tf32 (HW truncation no-op).
// Block tile 128x128, BK=32, 2-stage cp.async, 128 threads (4 warps, 2x2),
// warp tile 64x64, ONE __syncthreads per K-iter, 2 CTAs/SM.
// roundOut: round C to tf32 at store (for tensors consumed by later mmas).
// ---------------------------------------------------------------------------
#define GEMM_SMEM_FLOATS (2*128*36 + 2*32*132)   // 17664
#define GEMM_SMEM_BYTES  (GEMM_SMEM_FLOATS * 4)  // 70656

__global__ __launch_bounds__(128, 2) void gemm_rr_async(
    const float* __restrict__ A, const float* __restrict__ B,
    const float* __restrict__ bias, float* __restrict__ C,
    int K, int lda, int ldb, int ldc, int roundOut)
{
    extern __shared__ float sm[];
    float* As0 = sm;                 // [2][128*36]
    float* Bs0 = sm + 2 * 128 * 36;  // [2][32*132]
    const int tid = threadIdx.x;
    const int wid = tid >> 5;
    const int wr = wid >> 1;       // 0..1 (64-row half)
    const int wc = wid & 1;        // 0..1 (64-col half)
    const int row0 = blockIdx.y * 128;
    const int col0 = blockIdx.x * 128;

    wmma::fragment<wmma::accumulator, 16, 16, 8, float> acc[4][4];
#pragma unroll
    for (int i = 0; i < 4; i++)
#pragma unroll
        for (int j = 0; j < 4; j++) wmma::fill_fragment(acc[i][j], 0.0f);

    const int NT = K >> 5;

    auto prefetch = [&](int it, int s) {
        const int k0 = it << 5;
        float* As = As0 + s * (128 * 36);
        float* Bs = Bs0 + s * (32 * 132);
#pragma unroll
        for (int t = 0; t < 8; t++) {
            int f = tid + (t << 7);              // 1024 float4s (128x32)
            int r = f >> 3, c = (f & 7) << 2;
            CPA(smem_u32(As + r * 36 + c), A + (size_t)(row0 + r) * lda + k0 + c);
        }
#pragma unroll
        for (int t = 0; t < 8; t++) {
            int f = tid + (t << 7);              // 1024 float4s (32x128)
            int r = f >> 5, c = (f & 31) << 2;
            CPA(smem_u32(Bs + r * 132 + c), B + (size_t)(k0 + r) * ldb + col0 + c);
        }
        CPCOMMIT();
    };

    prefetch(0, 0);
    for (int it = 0; it < NT; it++) {
        const int s = it & 1;
        CPWAIT0();
        __syncthreads();
        if (it + 1 < NT) prefetch(it + 1, s ^ 1);
        float* As = As0 + s * (128 * 36);
        float* Bs = Bs0 + s * (32 * 132);
#pragma unroll
        for (int kk = 0; kk < 4; kk++) {
            wmma::fragment<wmma::matrix_a, 16, 16, 8, wmma::precision::tf32, wmma::row_major> af[4];
#pragma unroll
            for (int i = 0; i < 4; i++)
                wmma::load_matrix_sync(af[i], As + (wr * 64 + i * 16) * 36 + kk * 8, 36);
#pragma unroll
            for (int j = 0; j < 4; j++) {
                wmma::fragment<wmma::matrix_b, 16, 16, 8, wmma::precision::tf32, wmma::row_major> bf;
                wmma::load_matrix_sync(bf, Bs + (kk * 8) * 132 + wc * 64 + j * 16, 132);
#pragma unroll
                for (int i = 0; i < 4; i++)
                    wmma::mma_sync(acc[i][j], af[i], bf, acc[i][j]);
            }
        }
        // No trailing barrier: stage s is next overwritten at it+2, behind
        // the top __syncthreads of it+1 (all warps past this compute).
    }

    // Epilogue: per-warp smem staging (64x64, ld 68), fused bias, float4 stores.
    __syncthreads();
    float* stg = sm + wid * (64 * 68);
#pragma unroll
    for (int i = 0; i < 4; i++)
#pragma unroll
        for (int j = 0; j < 4; j++)
            wmma::store_matrix_sync(stg + (i * 16) * 68 + j * 16, acc[i][j], 68, wmma::mem_row_major);
    __syncwarp();
    const int lane = tid & 31;
    const int cbase = col0 + wc * 64;
#pragma unroll
    for (int t = 0; t < 32; t++) {
        int f = lane + t * 32;               // 1024 float4s (64x16)
        int r = f >> 4, c = (f & 15) << 2;
        float4 v = *(float4*)(stg + r * 68 + c);
        if (bias) {
            v.x += bias[cbase + c + 0];
            v.y += bias[cbase + c + 1];
            v.z += bias[cbase + c + 2];
            v.w += bias[cbase + c + 3];
        }
        if (roundOut) {
            v.x = tf32r(v.x); v.y = tf32r(v.y); v.z = tf32r(v.z); v.w = tf32r(v.w);
        }
        *(float4*)(C + (size_t)(row0 + wr * 64 + r) * ldc + cbase + c) = v;
    }
}

// ---------------------------------------------------------------------------
// Compose split-K: part[z] = wq[:, z*128:(z+1)*128] @ wuk[:, z*128:(z+1)*128]^T
// (M=1024, N=512, K-chunk=128). 256 CTAs -> full chip. Partials in fp32.
// ---------------------------------------------------------------------------
__global__ __launch_bounds__(256) void gemm_rt_splitk(
    const float* __restrict__ A, const float* __restrict__ Bt,
    float* __restrict__ part, int K)
{
    __shared__ float As[128 * 36];
    __shared__ float Bs[128 * 36];
    const int tid = threadIdx.x;
    const int wid = tid >> 5;
    const int wr = wid >> 1;
    const int wc = wid & 1;
    const int row0 = blockIdx.y * 128;
    const int col0 = blockIdx.x * 128;
    const int z = blockIdx.z;
    const int kbeg = z * (CD / NSPLIT);
    const int kend = kbeg + (CD / NSPLIT);
    float* Cz = part + (size_t)z * CD * CL;

    wmma::fragment<wmma::accumulator, 16, 16, 8, float> acc[2][4];
#pragma unroll
    for (int i = 0; i < 2; i++)
#pragma unroll
        for (int j = 0; j < 4; j++) wmma::fill_fragment(acc[i][j], 0.0f);

    for (int k0 = kbeg; k0 < kend; k0 += 32) {
#pragma unroll
        for (int t = 0; t < 4; t++) {
            int f = tid + t * 256;
            int r = f >> 3, c = (f & 7) << 2;
            float4 v = *(const float4*)(A + (size_t)(row0 + r) * K + k0 + c);
            v.x = tf32r(v.x); v.y = tf32r(v.y); v.z = tf32r(v.z); v.w = tf32r(v.w);
            *(float4*)(As + r * 36 + c) = v;
        }
#pragma unroll
        for (int t = 0; t < 4; t++) {
            int f = tid + t * 256;
            int r = f >> 3, c = (f & 7) << 2;
            float4 v = *(const float4*)(Bt + (size_t)(col0 + r) * K + k0 + c);
            v.x = tf32r(v.x); v.y = tf32r(v.y); v.z = tf32r(v.z); v.w = tf32r(v.w);
            *(float4*)(Bs + r * 36 + c) = v;
        }
        __syncthreads();
#pragma unroll
        for (int kk = 0; kk < 4; kk++) {
            wmma::fragment<wmma::matrix_a, 16, 16, 8, wmma::precision::tf32, wmma::row_major> af[2];
#pragma unroll
            for (int i = 0; i < 2; i++)
                wmma::load_matrix_sync(af[i], As + (wr * 32 + i * 16) * 36 + kk * 8, 36);
#pragma unroll
            for (int j = 0; j < 4; j++) {
                wmma::fragment<wmma::matrix_b, 16, 16, 8, wmma::precision::tf32, wmma::col_major> bf;
                wmma::load_matrix_sync(bf, Bs + (wc * 64 + j * 16) * 36 + kk * 8, 36);
#pragma unroll
                for (int i = 0; i < 2; i++)
                    wmma::mma_sync(acc[i][j], af[i], bf, acc[i][j]);
            }
        }
        __syncthreads();
    }
#pragma unroll
    for (int i = 0; i < 2; i++)
#pragma unroll
        for (int j = 0; j < 4; j++)
            wmma::store_matrix_sync(
                Cz + (size_t)(row0 + wr * 32 + i * 16) * CL + col0 + wc * 64 + j * 16,
                acc[i][j], CL, wmma::mem_row_major);
}

// Wcat[r, c<512] = tf32r(sum_z part[z][r*512+c]); float4-vectorized.
__global__ void reduce_compose_kernel(const float* __restrict__ part,
                                      float* __restrict__ Wcat)
{
    int i = blockIdx.x * 256 + threadIdx.x;   // 131072 float4s
    int r = i >> 7, c = (i & 127) << 2;
    float4 s = make_float4(0.f, 0.f, 0.f, 0.f);
#pragma unroll
    for (int z = 0; z < NSPLIT; z++) {
        float4 v = *(const float4*)(part + (size_t)z * CD * CL + (size_t)r * CL + c);
        s.x += v.x; s.y += v.y; s.z += v.z; s.w += v.w;
    }
    s.x = tf32r(s.x); s.y = tf32r(s.y); s.z = tf32r(s.z); s.w = tf32r(s.w);
    *(float4*)(Wcat + (size_t)r * CD + c) = s;
}

// bcat[l] = sum_d bq[d]*wuk[l,d] for l<512, else 0.  (one warp per l)
__global__ void bcat_kernel(const float* __restrict__ bq,
                            const float* __restrict__ wuk,
                            float* __restrict__ bcat)
{
    int l = blockIdx.x * 4 + (threadIdx.x >> 5);
    int lane = threadIdx.x & 31;
    if (l < CL) {
        float s = 0.f;
        for (int d = lane; d < CD; d += 32) s += bq[d] * wuk[(size_t)l * CD + d];
#pragma unroll
        for (int o = 16; o > 0; o >>= 1) s += __shfl_xor_sync(0xffffffffu, s, o);
        if (lane == 0) bcat[l] = s;
    } else {
        if (lane == 0) bcat[l] = 0.f;
    }
}

// Copy w_ckv (1024x512) rounded into Wcat columns [512, 1024)
__global__ void copy_wckv_kernel(const float* __restrict__ w, float* __restrict__ Wcat)
{
    int idx = blockIdx.x * 256 + threadIdx.x;   // 131072 float4s
    int r = idx >> 7, c = (idx & 127) << 2;
    float4 v = *(const float4*)(w + (size_t)r * CL + c);
    v.x = tf32r(v.x); v.y = tf32r(v.y); v.z = tf32r(v.z); v.w = tf32r(v.w);
    *(float4*)(Wcat + (size_t)r * CD + CL + c) = v;
}

// ---------------------------------------------------------------------------
// Flash attention, register-resident (FA2-style, raw mma.m16n8k8.tf32).
// All operands arrive PRE-ROUNDED to tf32 -> no in-loop rounding passes,
// ONE __syncthreads per KV-iter. O accumulator + softmax state in registers;
// only P round-trips smem (per-warp private rows). z stored tf32-rounded.
// ---------------------------------------------------------------------------
#define ATT_SMEM_FLOATS (64*36 + 2*64*36 + 2*64*72 + 64*68 + 64 + 2*64)  // 20672
#define ATT_SMEM_BYTES  (ATT_SMEM_FLOATS * 4)   // 82688

__global__ __launch_bounds__(128) void attn_kernel(
    const float* __restrict__ qc, const float* __restrict__ vbuf,
    const float* __restrict__ mask, float* __restrict__ z)
{
    extern __shared__ float sm[];
    float* Qs   = sm;                   // 64 x 36
    float* Ks0  = Qs + 64 * 36;         // 2 x (64 x 36)
    float* Vs0  = Ks0 + 2 * 64 * 36;    // 2 x (64 x 72)
    float* Ps   = Vs0 + 2 * 64 * 72;    // 64 x 68 (probs, tf32)
    float* mqv  = Ps + 64 * 68;         // 64
    float* mks0 = mqv + 64;             // 2 x 64

    const int tid = threadIdx.x;
    const int w = tid >> 5;
    const int lane = tid & 31;
    const int g = lane >> 2;            // 0..7 (row group)
    const int t = lane & 3;             // 0..3
    const int qt = blockIdx.x, h = blockIdx.y, b = blockIdx.z;
    const int q0 = qt * 64;
    const float SCALE = 0.17677669529663687f;   // 1/sqrt(32)

    auto prefetch = [&](int kt, int s) {
        const int s0 = kt * 64;
        float* Ks = Ks0 + s * (64 * 36);
        float* Vs = Vs0 + s * (64 * 72);
        const float* kbase = qc + ((size_t)b * CS + s0) * CD + CL + h * CLHD;
#pragma unroll
        for (int i = 0; i < 4; i++) {
            int f = tid + i * 128;
            int r = f >> 3, c = (f & 7) << 2;
            CPA(smem_u32(Ks + r * 36 + c), kbase + (size_t)r * CD + c);
        }
        const float* vbase = vbuf + ((size_t)b * CS + s0) * CD + h * CHD;
#pragma unroll
        for (int i = 0; i < 8; i++) {
            int f = tid + i * 128;
            int r = f >> 4, c = (f & 15) << 2;
            CPA(smem_u32(Vs + r * 72 + c), vbase + (size_t)r * CD + c);
        }
        if (tid < 16)
            CPA(smem_u32(mks0 + s * 64 + tid * 4), mask + (size_t)b * CS + s0 + tid * 4);
        CPCOMMIT();
    };

    // Issue Q tile + q-mask, then stage-0 K/V
    {
        const float* qbase = qc + ((size_t)b * CS + q0) * CD + h * CLHD;
#pragma unroll
        for (int i = 0; i < 4; i++) {
            int f = tid + i * 128;
            int r = f >> 3, c = (f & 7) << 2;
            CPA(smem_u32(Qs + r * 36 + c), qbase + (size_t)r * CD + c);
        }
        if (tid < 16)
            CPA(smem_u32(mqv + tid * 4), mask + (size_t)b * CS + q0 + tid * 4);
        CPCOMMIT();
    }
    prefetch(0, 0);
    CPWAIT0();
    __syncthreads();

    // Hoist Q fragments (already tf32-rounded by the producer GEMM)
    uint32_t qa[4][4];
    {
        const float* Qw = Qs + (w * 16) * 36;
#pragma unroll
        for (int kk = 0; kk < 4; kk++) {
            qa[kk][0] = __float_as_uint(Qw[(size_t)g * 36 + kk * 8 + t]);
            qa[kk][1] = __float_as_uint(Qw[(size_t)(g + 8) * 36 + kk * 8 + t]);
            qa[kk][2] = __float_as_uint(Qw[(size_t)g * 36 + kk * 8 + t + 4]);
            qa[kk][3] = __float_as_uint(Qw[(size_t)(g + 8) * 36 + kk * 8 + t + 4]);
        }
    }
    const float mq0 = mqv[w * 16 + g];
    const float mq1 = mqv[w * 16 + g + 8];

    float o[8][4];
#pragma unroll
    for (int j = 0; j < 8; j++)
#pragma unroll
        for (int e = 0; e < 4; e++) o[j][e] = 0.f;
    float m0 = -1e30f, m1 = -1e30f, l0 = 0.f, l1 = 0.f;
    float* Pw = Ps + (w * 16) * 68;

    for (int kt = 0; kt < 16; kt++) {
        const int s = kt & 1;
        if (kt) { CPWAIT0(); __syncthreads(); }
        if (kt + 1 < 16) prefetch(kt + 1, s ^ 1);
        const float* Vs  = Vs0 + s * (64 * 72);
        const float* Ksb = Ks0 + s * (64 * 36);
        const float* mks = mks0 + s * 64;

        // S = Q @ K^T : 8 n-tiles x 4 k-tiles of m16n8k8
        float sv[8][4];
#pragma unroll
        for (int j = 0; j < 8; j++) {
            sv[j][0] = sv[j][1] = sv[j][2] = sv[j][3] = 0.f;
            const float* krow = Ksb + (size_t)(j * 8 + g) * 36;
#pragma unroll
            for (int kk = 0; kk < 4; kk++) {
                uint32_t b0 = __float_as_uint(krow[kk * 8 + t]);
                uint32_t b1 = __float_as_uint(krow[kk * 8 + t + 4]);
                MMA_TF32(sv[j], qa[kk][0], qa[kk][1], qa[kk][2], qa[kk][3], b0, b1);
            }
        }

        // Mask + online softmax in registers
        float rmax0 = -1e30f, rmax1 = -1e30f;
#pragma unroll
        for (int j = 0; j < 8; j++) {
            float2 mk2 = *(const float2*)(mks + j * 8 + t * 2);
            sv[j][0] = sv[j][0] * SCALE + fminf(1.f, mq0 + mk2.x) * M_ALPHA;
            sv[j][1] = sv[j][1] * SCALE + fminf(1.f, mq0 + mk2.y) * M_ALPHA;
            sv[j][2] = sv[j][2] * SCALE + fminf(1.f, mq1 + mk2.x) * M_ALPHA;
            sv[j][3] = sv[j][3] * SCALE + fminf(1.f, mq1 + mk2.y) * M_ALPHA;
            rmax0 = fmaxf(rmax0, fmaxf(sv[j][0], sv[j][1]));
            rmax1 = fmaxf(rmax1, fmaxf(sv[j][2], sv[j][3]));
        }
        rmax0 = fmaxf(rmax0, __shfl_xor_sync(0xffffffffu, rmax0, 1));
        rmax0 = fmaxf(rmax0, __shfl_xor_sync(0xffffffffu, rmax0, 2));
        rmax1 = fmaxf(rmax1, __shfl_xor_sync(0xffffffffu, rmax1, 1));
        rmax1 = fmaxf(rmax1, __shfl_xor_sync(0xffffffffu, rmax1, 2));
        const float nm0 = fmaxf(m0, rmax0), nm1 = fmaxf(m1, rmax1);
        const float corr0 = __expf(m0 - nm0), corr1 = __expf(m1 - nm1);
        float ps0 = 0.f, ps1 = 0.f;
#pragma unroll
        for (int j = 0; j < 8; j++) {
            float p00 = __expf(sv[j][0] - nm0);
            float p01 = __expf(sv[j][1] - nm0);
            float p10 = __expf(sv[j][2] - nm1);
            float p11 = __expf(sv[j][3] - nm1);
            ps0 += p00 + p01;
            ps1 += p10 + p11;
            Pw[(size_t)g * 68 + j * 8 + t * 2]           = tf32r(p00);
            Pw[(size_t)g * 68 + j * 8 + t * 2 + 1]       = tf32r(p01);
            Pw[(size_t)(g + 8) * 68 + j * 8 + t * 2]     = tf32r(p10);
            Pw[(size_t)(g + 8) * 68 + j * 8 + t * 2 + 1] = tf32r(p11);
            o[j][0] *= corr0; o[j][1] *= corr0;
            o[j][2] *= corr1; o[j][3] *= corr1;
        }
        ps0 += __shfl_xor_sync(0xffffffffu, ps0, 1);
        ps0 += __shfl_xor_sync(0xffffffffu, ps0, 2);
        ps1 += __shfl_xor_sync(0xffffffffu, ps1, 1);
        ps1 += __shfl_xor_sync(0xffffffffu, ps1, 2);
        l0 = l0 * corr0 + ps0;
        l1 = l1 * corr1 + ps1;
        m0 = nm0; m1 = nm1;
        __syncwarp();

        // O += P @ V : 8 k-tiles x 8 n-tiles of m16n8k8, O in registers
#pragma unroll
        for (int kk = 0; kk < 8; kk++) {
            uint32_t a0 = __float_as_uint(Pw[(size_t)g * 68 + kk * 8 + t]);
            uint32_t a1 = __float_as_uint(Pw[(size_t)(g + 8) * 68 + kk * 8 + t]);
            uint32_t a2 = __float_as_uint(Pw[(size_t)g * 68 + kk * 8 + t + 4]);
            uint32_t a3 = __float_as_uint(Pw[(size_t)(g + 8) * 68 + kk * 8 + t + 4]);
            const float* vr0 = Vs + (size_t)(kk * 8 + t) * 72;
            const float* vr1 = Vs + (size_t)(kk * 8 + t + 4) * 72;
#pragma unroll
            for (int j = 0; j < 8; j++) {
                uint32_t b0 = __float_as_uint(vr0[j * 8 + g]);
                uint32_t b1 = __float_as_uint(vr1[j * 8 + g]);
                MMA_TF32(o[j], a0, a1, a2, a3, b0, b1);
            }
        }
    }

    // Normalize, round to tf32 (consumed by out-GEMM), write z
    {
        const float inv0 = 1.0f / l0, inv1 = 1.0f / l1;
        float* zr0 = z + ((size_t)b * CS + q0 + w * 16 + g) * CD + h * CHD;
        float* zr1 = zr0 + 8 * CD;
#pragma unroll
        for (int j = 0; j < 8; j++) {
            float2 v0 = make_float2(tf32r(o[j][0] * inv0), tf32r(o[j][1] * inv0));
            float2 v1 = make_float2(tf32r(o[j][2] * inv1), tf32r(o[j][3] * inv1));
            *(float2*)(zr0 + j * 8 + t * 2) = v0;
            *(float2*)(zr1 + j * 8 + t * 2) = v1;
        }
    }
}

// ---------------------------------------------------------------------------
// Launch
// ---------------------------------------------------------------------------
extern "C" void kernel_launch(void* const* d_in, const int* in_sizes, int n_in,
                              void* d_out, int out_size)
{
    (void)in_sizes; (void)n_in; (void)out_size;
    const float* x     = (const float*)d_in[0];
    const float* mask  = (const float*)d_in[1];
    const float* wq    = (const float*)d_in[2];
    const float* bq    = (const float*)d_in[3];
    const float* w_ckv = (const float*)d_in[4];
    const float* wuk   = (const float*)d_in[5];
    const float* wuv   = (const float*)d_in[6];
    const float* wo    = (const float*)d_in[7];
    const float* bo    = (const float*)d_in[8];
    float* out = (float*)d_out;

    float *pWcat, *pbcat, *pqc, *pv, *pz, *pxr, *pwuvr, *pwor, *ppart;
    cudaGetSymbolAddress((void**)&pWcat,  g_Wcat);
    cudaGetSymbolAddress((void**)&pbcat,  g_bcat);
    cudaGetSymbolAddress((void**)&pqc,    g_qc);
    cudaGetSymbolAddress((void**)&pv,     g_v);
    cudaGetSymbolAddress((void**)&pz,     g_z);
    cudaGetSymbolAddress((void**)&pxr,    g_xr);
    cudaGetSymbolAddress((void**)&pwuvr,  g_wuvr);
    cudaGetSymbolAddress((void**)&pwor,   g_wor);
    cudaGetSymbolAddress((void**)&ppart,  g_part);

    cudaFuncSetAttribute(gemm_rr_async,
                         cudaFuncAttributeMaxDynamicSharedMemorySize, GEMM_SMEM_BYTES);
    cudaFuncSetAttribute(attn_kernel,
                         cudaFuncAttributeMaxDynamicSharedMemorySize, ATT_SMEM_BYTES);

    // 0. tf32-rounded copies of GEMM operands
    round_copy_kernel<<<(MROWS * CD / 4 + 255) / 256, 256>>>(x,   pxr,   MROWS * CD / 4);
    round_copy_kernel<<<(CL * CD / 4 + 255) / 256, 256>>>(wuv, pwuvr, CL * CD / 4);
    round_copy_kernel<<<(CD * CD / 4 + 255) / 256, 256>>>(wo,  pwor,  CD * CD / 4);
    // 1. Wcat[:, 0:512] = rna(wq @ wuk^T) via split-K partials + reduce
    gemm_rt_splitk<<<dim3(CL / 128, CD / 128, NSPLIT), 256>>>(wq, wuk, ppart, CD);
    reduce_compose_kernel<<<CD * CL / 4 / 256, 256>>>(ppart, pWcat);
    // 2. Wcat[:, 512:1024] = rna(w_ckv) ; bcat = [bq @ wuk^T | 0]
    copy_wckv_kernel<<<512, 256>>>(w_ckv, pWcat);
    bcat_kernel<<<CD / 4, 128>>>(bq, wuk, pbcat);
    // 3. qc = rna(x @ Wcat + bcat)   (8192x1024, K=1024) -> [q_latent | combined]
    gemm_rr_async<<<dim3(CD / 128, MROWS / 128), 128, GEMM_SMEM_BYTES>>>(
        pxr, pWcat, pbcat, pqc, CD, CD, CD, CD, 1);
    // 4. v = rna(combined @ wuv)     (8192x1024, K=512)
    gemm_rr_async<<<dim3(CD / 128, MROWS / 128), 128, GEMM_SMEM_BYTES>>>(
        pqc + CL, pwuvr, nullptr, pv, CL, CD, CD, CD, 1);
    // 5. attention -> z (tf32-rounded)
    attn_kernel<<<dim3(CS / 64, CH, CB), 128, ATT_SMEM_BYTES>>>(pqc, pv, mask, pz);
    // 6. out = z @ wo + bo           (8192x1024, K=1024, fp32 out)
    gemm_rr_async<<<dim3(CD / 128, MROWS / 128), 128, GEMM_SMEM_BYTES>>>(
        pz, pwor, bo, out, CD, CD, CD, CD, 0);
}

// round 16
// speedup vs baseline: 1.4133x; 1.4133x over previous
#include <cuda_runtime.h>
#include <mma.h>
#include <cstdint>

using namespace nvcuda;

// Problem constants
#define CB 8
#define CS 1024
#define CD 1024
#define CH 16
#define CHD 64
#define CL 512
#define CLHD 32
#define MROWS (CB*CS)   // 8192
#define M_ALPHA (-1000000000.0f)
#define NSPLIT 8        // split-K factor for the compose GEMM

// ---------------------------------------------------------------------------
// Scratch (static device globals — no runtime allocation allowed)
// ---------------------------------------------------------------------------
__device__ float g_Wcat[(size_t)CD*CD];     // [Wql | w_ckv] tf32-rounded   4MB
__device__ float g_bcat[CD];                // [bql | 0]
__device__ float g_qc[(size_t)MROWS*CD];    // [q_latent | combined] (tf32) 32MB
__device__ float g_v[(size_t)MROWS*CD];     // v (tf32-rounded)             32MB
__device__ float g_z[(size_t)MROWS*CD];     // attention output (tf32)      32MB
__device__ float g_xr[(size_t)MROWS*CD];    // x tf32-rounded               32MB
__device__ float g_wuvr[(size_t)CL*CD];     // wuv tf32-rounded             2MB
__device__ float g_wor[(size_t)CD*CD];      // wo tf32-rounded              4MB
__device__ float g_part[(size_t)NSPLIT*CD*CL]; // compose split-K partials  16MB

__device__ __forceinline__ uint32_t smem_u32(const void* p) {
    return (uint32_t)__cvta_generic_to_shared(p);
}
__device__ __forceinline__ float tf32r(float x) {
    uint32_t u;
    asm("cvt.rna.tf32.f32 %0, %1;" : "=r"(u) : "f"(x));
    return __uint_as_float(u);
}
#define CPA(dst, src) asm volatile("cp.async.cg.shared.global [%0], [%1], 16;\n" :: "r"(dst), "l"(src))
#define CPCOMMIT()    asm volatile("cp.async.commit_group;\n")
#define CPWAIT0()     asm volatile("cp.async.wait_group 0;\n")

#define MMA_TF32(d, a0,a1,a2,a3, b0,b1) \
    asm volatile("mma.sync.aligned.m16n8k8.row.col.f32.tf32.tf32.f32 " \
        "{%0,%1,%2,%3}, {%4,%5,%6,%7}, {%8,%9}, {%0,%1,%2,%3};" \
        : "+f"(d[0]),"+f"(d[1]),"+f"(d[2]),"+f"(d[3]) \
        : "r"(a0),"r"(a1),"r"(a2),"r"(a3), "r"(b0),"r"(b1))

// Round-copy: dst = rna_tf32(src), float4-vectorized. n4 = count of float4s.
__global__ void round_copy_kernel(const float* __restrict__ src,
                                  float* __restrict__ dst, int n4)
{
    int i = blockIdx.x * 256 + threadIdx.x;
    if (i < n4) {
        float4 v = *(const float4*)(src + (size_t)i * 4);
        v.x = tf32r(v.x); v.y = tf32r(v.y); v.z = tf32r(v.z); v.w = tf32r(v.w);
        *(float4*)(dst + (size_t)i * 4) = v;
    }
}

// ---------------------------------------------------------------------------
// Pipelined GEMM (R12 config — measured best): C(M,N) = A(M,K) @ B(K,N)
// (+ bias[col]), row-major, explicit leading dims. Operands PRE-ROUNDED tf32.
// Block tile 128x128, BK=32, 2-stage cp.async, 256 threads (8 warps, 4x2),
// warp tile 32x64, ONE __syncthreads per K-iter, 2 CTAs/SM.
// ---------------------------------------------------------------------------
#define GEMM_SMEM_FLOATS (2*128*36 + 2*32*132)   // 17664
#define GEMM_SMEM_BYTES  (GEMM_SMEM_FLOATS * 4)  // 70656

__global__ __launch_bounds__(256, 2) void gemm_rr_async(
    const float* __restrict__ A, const float* __restrict__ B,
    const float* __restrict__ bias, float* __restrict__ C,
    int K, int lda, int ldb, int ldc, int roundOut)
{
    extern __shared__ float sm[];
    float* As0 = sm;                 // [2][128*36]
    float* Bs0 = sm + 2 * 128 * 36;  // [2][32*132]
    const int tid = threadIdx.x;
    const int wid = tid >> 5;
    const int wr = wid >> 1;       // 0..3
    const int wc = wid & 1;        // 0..1
    const int row0 = blockIdx.y * 128;
    const int col0 = blockIdx.x * 128;

    wmma::fragment<wmma::accumulator, 16, 16, 8, float> acc[2][4];
#pragma unroll
    for (int i = 0; i < 2; i++)
#pragma unroll
        for (int j = 0; j < 4; j++) wmma::fill_fragment(acc[i][j], 0.0f);

    const int NT = K >> 5;

    auto prefetch = [&](int it, int s) {
        const int k0 = it << 5;
        float* As = As0 + s * (128 * 36);
        float* Bs = Bs0 + s * (32 * 132);
#pragma unroll
        for (int t = 0; t < 4; t++) {
            int f = tid + (t << 8);              // 1024 float4s (128x32)
            int r = f >> 3, c = (f & 7) << 2;
            CPA(smem_u32(As + r * 36 + c), A + (size_t)(row0 + r) * lda + k0 + c);
        }
#pragma unroll
        for (int t = 0; t < 4; t++) {
            int f = tid + (t << 8);              // 1024 float4s (32x128)
            int r = f >> 5, c = (f & 31) << 2;
            CPA(smem_u32(Bs + r * 132 + c), B + (size_t)(k0 + r) * ldb + col0 + c);
        }
        CPCOMMIT();
    };

    prefetch(0, 0);
    for (int it = 0; it < NT; it++) {
        const int s = it & 1;
        CPWAIT0();
        __syncthreads();
        if (it + 1 < NT) prefetch(it + 1, s ^ 1);
        float* As = As0 + s * (128 * 36);
        float* Bs = Bs0 + s * (32 * 132);
#pragma unroll
        for (int kk = 0; kk < 4; kk++) {
            wmma::fragment<wmma::matrix_a, 16, 16, 8, wmma::precision::tf32, wmma::row_major> af[2];
#pragma unroll
            for (int i = 0; i < 2; i++)
                wmma::load_matrix_sync(af[i], As + (wr * 32 + i * 16) * 36 + kk * 8, 36);
#pragma unroll
            for (int j = 0; j < 4; j++) {
                wmma::fragment<wmma::matrix_b, 16, 16, 8, wmma::precision::tf32, wmma::row_major> bf;
                wmma::load_matrix_sync(bf, Bs + (kk * 8) * 132 + wc * 64 + j * 16, 132);
#pragma unroll
                for (int i = 0; i < 2; i++)
                    wmma::mma_sync(acc[i][j], af[i], bf, acc[i][j]);
            }
        }
        // No trailing barrier: stage s is next overwritten at it+2, behind
        // the top __syncthreads of it+1 (all warps past this compute).
    }

    // Epilogue: per-warp smem staging (32x64, ld 68), fused bias, float4 stores.
    __syncthreads();
    float* stg = sm + wid * (32 * 68);
#pragma unroll
    for (int i = 0; i < 2; i++)
#pragma unroll
        for (int j = 0; j < 4; j++)
            wmma::store_matrix_sync(stg + (i * 16) * 68 + j * 16, acc[i][j], 68, wmma::mem_row_major);
    __syncwarp();
    const int lane = tid & 31;
    const int cbase = col0 + wc * 64;
#pragma unroll
    for (int t = 0; t < 16; t++) {
        int f = lane + t * 32;               // 512 float4s (32x16)
        int r = f >> 4, c = (f & 15) << 2;
        float4 v = *(float4*)(stg + r * 68 + c);
        if (bias) {
            v.x += bias[cbase + c + 0];
            v.y += bias[cbase + c + 1];
            v.z += bias[cbase + c + 2];
            v.w += bias[cbase + c + 3];
        }
        if (roundOut) {
            v.x = tf32r(v.x); v.y = tf32r(v.y); v.z = tf32r(v.z); v.w = tf32r(v.w);
        }
        *(float4*)(C + (size_t)(row0 + wr * 32 + r) * ldc + cbase + c) = v;
    }
}

// ---------------------------------------------------------------------------
// Compose split-K: part[z] = wq[:, z-chunk] @ wuk[:, z-chunk]^T
// (M=1024, N=512, K-chunk=128). 256 CTAs -> full chip. Partials in fp32.
// ---------------------------------------------------------------------------
__global__ __launch_bounds__(256) void gemm_rt_splitk(
    const float* __restrict__ A, const float* __restrict__ Bt,
    float* __restrict__ part, int K)
{
    __shared__ float As[128 * 36];
    __shared__ float Bs[128 * 36];
    const int tid = threadIdx.x;
    const int wid = tid >> 5;
    const int wr = wid >> 1;
    const int wc = wid & 1;
    const int row0 = blockIdx.y * 128;
    const int col0 = blockIdx.x * 128;
    const int z = blockIdx.z;
    const int kbeg = z * (CD / NSPLIT);
    const int kend = kbeg + (CD / NSPLIT);
    float* Cz = part + (size_t)z * CD * CL;

    wmma::fragment<wmma::accumulator, 16, 16, 8, float> acc[2][4];
#pragma unroll
    for (int i = 0; i < 2; i++)
#pragma unroll
        for (int j = 0; j < 4; j++) wmma::fill_fragment(acc[i][j], 0.0f);

    for (int k0 = kbeg; k0 < kend; k0 += 32) {
#pragma unroll
        for (int t = 0; t < 4; t++) {
            int f = tid + t * 256;
            int r = f >> 3, c = (f & 7) << 2;
            float4 v = *(const float4*)(A + (size_t)(row0 + r) * K + k0 + c);
            v.x = tf32r(v.x); v.y = tf32r(v.y); v.z = tf32r(v.z); v.w = tf32r(v.w);
            *(float4*)(As + r * 36 + c) = v;
        }
#pragma unroll
        for (int t = 0; t < 4; t++) {
            int f = tid + t * 256;
            int r = f >> 3, c = (f & 7) << 2;
            float4 v = *(const float4*)(Bt + (size_t)(col0 + r) * K + k0 + c);
            v.x = tf32r(v.x); v.y = tf32r(v.y); v.z = tf32r(v.z); v.w = tf32r(v.w);
            *(float4*)(Bs + r * 36 + c) = v;
        }
        __syncthreads();
#pragma unroll
        for (int kk = 0; kk < 4; kk++) {
            wmma::fragment<wmma::matrix_a, 16, 16, 8, wmma::precision::tf32, wmma::row_major> af[2];
#pragma unroll
            for (int i = 0; i < 2; i++)
                wmma::load_matrix_sync(af[i], As + (wr * 32 + i * 16) * 36 + kk * 8, 36);
#pragma unroll
            for (int j = 0; j < 4; j++) {
                wmma::fragment<wmma::matrix_b, 16, 16, 8, wmma::precision::tf32, wmma::col_major> bf;
                wmma::load_matrix_sync(bf, Bs + (wc * 64 + j * 16) * 36 + kk * 8, 36);
#pragma unroll
                for (int i = 0; i < 2; i++)
                    wmma::mma_sync(acc[i][j], af[i], bf, acc[i][j]);
            }
        }
        __syncthreads();
    }
#pragma unroll
    for (int i = 0; i < 2; i++)
#pragma unroll
        for (int j = 0; j < 4; j++)
            wmma::store_matrix_sync(
                Cz + (size_t)(row0 + wr * 32 + i * 16) * CL + col0 + wc * 64 + j * 16,
                acc[i][j], CL, wmma::mem_row_major);
}

// Wcat[r, c<512] = tf32r(sum_z part[z][r*512+c]); float4-vectorized.
__global__ void reduce_compose_kernel(const float* __restrict__ part,
                                      float* __restrict__ Wcat)
{
    int i = blockIdx.x * 256 + threadIdx.x;   // 131072 float4s
    int r = i >> 7, c = (i & 127) << 2;
    float4 s = make_float4(0.f, 0.f, 0.f, 0.f);
#pragma unroll
    for (int z = 0; z < NSPLIT; z++) {
        float4 v = *(const float4*)(part + (size_t)z * CD * CL + (size_t)r * CL + c);
        s.x += v.x; s.y += v.y; s.z += v.z; s.w += v.w;
    }
    s.x = tf32r(s.x); s.y = tf32r(s.y); s.z = tf32r(s.z); s.w = tf32r(s.w);
    *(float4*)(Wcat + (size_t)r * CD + c) = s;
}

// bcat[l] = sum_d bq[d]*wuk[l,d] for l<512, else 0.  (one warp per l)
__global__ void bcat_kernel(const float* __restrict__ bq,
                            const float* __restrict__ wuk,
                            float* __restrict__ bcat)
{
    int l = blockIdx.x * 4 + (threadIdx.x >> 5);
    int lane = threadIdx.x & 31;
    if (l < CL) {
        float s = 0.f;
        for (int d = lane; d < CD; d += 32) s += bq[d] * wuk[(size_t)l * CD + d];
#pragma unroll
        for (int o = 16; o > 0; o >>= 1) s += __shfl_xor_sync(0xffffffffu, s, o);
        if (lane == 0) bcat[l] = s;
    } else {
        if (lane == 0) bcat[l] = 0.f;
    }
}

// Copy w_ckv (1024x512) rounded into Wcat columns [512, 1024)
__global__ void copy_wckv_kernel(const float* __restrict__ w, float* __restrict__ Wcat)
{
    int idx = blockIdx.x * 256 + threadIdx.x;   // 131072 float4s
    int r = idx >> 7, c = (idx & 127) << 2;
    float4 v = *(const float4*)(w + (size_t)r * CL + c);
    v.x = tf32r(v.x); v.y = tf32r(v.y); v.z = tf32r(v.z); v.w = tf32r(v.w);
    *(float4*)(Wcat + (size_t)r * CD + CL + c) = v;
}

// ---------------------------------------------------------------------------
// Flash attention, register-resident (FA2-style, raw mma.m16n8k8.tf32).
// All operands arrive PRE-ROUNDED to tf32 -> no in-loop rounding passes,
// ONE __syncthreads per KV-iter. O accumulator + softmax state in registers;
// only P round-trips smem (per-warp private rows). z stored tf32-rounded.
// ---------------------------------------------------------------------------
#define ATT_SMEM_FLOATS (64*36 + 2*64*36 + 2*64*72 + 64*68 + 64 + 2*64)  // 20672
#define ATT_SMEM_BYTES  (ATT_SMEM_FLOATS * 4)   // 82688

__global__ __launch_bounds__(128) void attn_kernel(
    const float* __restrict__ qc, const float* __restrict__ vbuf,
    const float* __restrict__ mask, float* __restrict__ z)
{
    extern __shared__ float sm[];
    float* Qs   = sm;                   // 64 x 36
    float* Ks0  = Qs + 64 * 36;         // 2 x (64 x 36)
    float* Vs0  = Ks0 + 2 * 64 * 36;    // 2 x (64 x 72)
    float* Ps   = Vs0 + 2 * 64 * 72;    // 64 x 68 (probs, tf32)
    float* mqv  = Ps + 64 * 68;         // 64
    float* mks0 = mqv + 64;             // 2 x 64

    const int tid = threadIdx.x;
    const int w = tid >> 5;
    const int lane = tid & 31;
    const int g = lane >> 2;            // 0..7 (row group)
    const int t = lane & 3;             // 0..3
    const int qt = blockIdx.x, h = blockIdx.y, b = blockIdx.z;
    const int q0 = qt * 64;
    const float SCALE = 0.17677669529663687f;   // 1/sqrt(32)

    auto prefetch = [&](int kt, int s) {
        const int s0 = kt * 64;
        float* Ks = Ks0 + s * (64 * 36);
        float* Vs = Vs0 + s * (64 * 72);
        const float* kbase = qc + ((size_t)b * CS + s0) * CD + CL + h * CLHD;
#pragma unroll
        for (int i = 0; i < 4; i++) {
            int f = tid + i * 128;
            int r = f >> 3, c = (f & 7) << 2;
            CPA(smem_u32(Ks + r * 36 + c), kbase + (size_t)r * CD + c);
        }
        const float* vbase = vbuf + ((size_t)b * CS + s0) * CD + h * CHD;
#pragma unroll
        for (int i = 0; i < 8; i++) {
            int f = tid + i * 128;
            int r = f >> 4, c = (f & 15) << 2;
            CPA(smem_u32(Vs + r * 72 + c), vbase + (size_t)r * CD + c);
        }
        if (tid < 16)
            CPA(smem_u32(mks0 + s * 64 + tid * 4), mask + (size_t)b * CS + s0 + tid * 4);
        CPCOMMIT();
    };

    // Issue Q tile + q-mask, then stage-0 K/V
    {
        const float* qbase = qc + ((size_t)b * CS + q0) * CD + h * CLHD;
#pragma unroll
        for (int i = 0; i < 4; i++) {
            int f = tid + i * 128;
            int r = f >> 3, c = (f & 7) << 2;
            CPA(smem_u32(Qs + r * 36 + c), qbase + (size_t)r * CD + c);
        }
        if (tid < 16)
            CPA(smem_u32(mqv + tid * 4), mask + (size_t)b * CS + q0 + tid * 4);
        CPCOMMIT();
    }
    prefetch(0, 0);
    CPWAIT0();
    __syncthreads();

    // Hoist Q fragments (already tf32-rounded by the producer GEMM)
    uint32_t qa[4][4];
    {
        const float* Qw = Qs + (w * 16) * 36;
#pragma unroll
        for (int kk = 0; kk < 4; kk++) {
            qa[kk][0] = __float_as_uint(Qw[(size_t)g * 36 + kk * 8 + t]);
            qa[kk][1] = __float_as_uint(Qw[(size_t)(g + 8) * 36 + kk * 8 + t]);
            qa[kk][2] = __float_as_uint(Qw[(size_t)g * 36 + kk * 8 + t + 4]);
            qa[kk][3] = __float_as_uint(Qw[(size_t)(g + 8) * 36 + kk * 8 + t + 4]);
        }
    }
    const float mq0 = mqv[w * 16 + g];
    const float mq1 = mqv[w * 16 + g + 8];

    float o[8][4];
#pragma unroll
    for (int j = 0; j < 8; j++)
#pragma unroll
        for (int e = 0; e < 4; e++) o[j][e] = 0.f;
    float m0 = -1e30f, m1 = -1e30f, l0 = 0.f, l1 = 0.f;
    float* Pw = Ps + (w * 16) * 68;

    for (int kt = 0; kt < 16; kt++) {
        const int s = kt & 1;
        if (kt) { CPWAIT0(); __syncthreads(); }
        if (kt + 1 < 16) prefetch(kt + 1, s ^ 1);
        const float* Vs  = Vs0 + s * (64 * 72);
        const float* Ksb = Ks0 + s * (64 * 36);
        const float* mks = mks0 + s * 64;

        // S = Q @ K^T : 8 n-tiles x 4 k-tiles of m16n8k8
        float sv[8][4];
#pragma unroll
        for (int j = 0; j < 8; j++) {
            sv[j][0] = sv[j][1] = sv[j][2] = sv[j][3] = 0.f;
            const float* krow = Ksb + (size_t)(j * 8 + g) * 36;
#pragma unroll
            for (int kk = 0; kk < 4; kk++) {
                uint32_t b0 = __float_as_uint(krow[kk * 8 + t]);
                uint32_t b1 = __float_as_uint(krow[kk * 8 + t + 4]);
                MMA_TF32(sv[j], qa[kk][0], qa[kk][1], qa[kk][2], qa[kk][3], b0, b1);
            }
        }

        // Mask + online softmax in registers
        float rmax0 = -1e30f, rmax1 = -1e30f;
#pragma unroll
        for (int j = 0; j < 8; j++) {
            float2 mk2 = *(const float2*)(mks + j * 8 + t * 2);
            sv[j][0] = sv[j][0] * SCALE + fminf(1.f, mq0 + mk2.x) * M_ALPHA;
            sv[j][1] = sv[j][1] * SCALE + fminf(1.f, mq0 + mk2.y) * M_ALPHA;
            sv[j][2] = sv[j][2] * SCALE + fminf(1.f, mq1 + mk2.x) * M_ALPHA;
            sv[j][3] = sv[j][3] * SCALE + fminf(1.f, mq1 + mk2.y) * M_ALPHA;
            rmax0 = fmaxf(rmax0, fmaxf(sv[j][0], sv[j][1]));
            rmax1 = fmaxf(rmax1, fmaxf(sv[j][2], sv[j][3]));
        }
        rmax0 = fmaxf(rmax0, __shfl_xor_sync(0xffffffffu, rmax0, 1));
        rmax0 = fmaxf(rmax0, __shfl_xor_sync(0xffffffffu, rmax0, 2));
        rmax1 = fmaxf(rmax1, __shfl_xor_sync(0xffffffffu, rmax1, 1));
        rmax1 = fmaxf(rmax1, __shfl_xor_sync(0xffffffffu, rmax1, 2));
        const float nm0 = fmaxf(m0, rmax0), nm1 = fmaxf(m1, rmax1);
        const float corr0 = __expf(m0 - nm0), corr1 = __expf(m1 - nm1);
        float ps0 = 0.f, ps1 = 0.f;
#pragma unroll
        for (int j = 0; j < 8; j++) {
            float p00 = __expf(sv[j][0] - nm0);
            float p01 = __expf(sv[j][1] - nm0);
            float p10 = __expf(sv[j][2] - nm1);
            float p11 = __expf(sv[j][3] - nm1);
            ps0 += p00 + p01;
            ps1 += p10 + p11;
            Pw[(size_t)g * 68 + j * 8 + t * 2]           = tf32r(p00);
            Pw[(size_t)g * 68 + j * 8 + t * 2 + 1]       = tf32r(p01);
            Pw[(size_t)(g + 8) * 68 + j * 8 + t * 2]     = tf32r(p10);
            Pw[(size_t)(g + 8) * 68 + j * 8 + t * 2 + 1] = tf32r(p11);
            o[j][0] *= corr0; o[j][1] *= corr0;
            o[j][2] *= corr1; o[j][3] *= corr1;
        }
        ps0 += __shfl_xor_sync(0xffffffffu, ps0, 1);
        ps0 += __shfl_xor_sync(0xffffffffu, ps0, 2);
        ps1 += __shfl_xor_sync(0xffffffffu, ps1, 1);
        ps1 += __shfl_xor_sync(0xffffffffu, ps1, 2);
        l0 = l0 * corr0 + ps0;
        l1 = l1 * corr1 + ps1;
        m0 = nm0; m1 = nm1;
        __syncwarp();

        // O += P @ V : 8 k-tiles x 8 n-tiles of m16n8k8, O in registers
#pragma unroll
        for (int kk = 0; kk < 8; kk++) {
            uint32_t a0 = __float_as_uint(Pw[(size_t)g * 68 + kk * 8 + t]);
            uint32_t a1 = __float_as_uint(Pw[(size_t)(g + 8) * 68 + kk * 8 + t]);
            uint32_t a2 = __float_as_uint(Pw[(size_t)g * 68 + kk * 8 + t + 4]);
            uint32_t a3 = __float_as_uint(Pw[(size_t)(g + 8) * 68 + kk * 8 + t + 4]);
            const float* vr0 = Vs + (size_t)(kk * 8 + t) * 72;
            const float* vr1 = Vs + (size_t)(kk * 8 + t + 4) * 72;
#pragma unroll
            for (int j = 0; j < 8; j++) {
                uint32_t b0 = __float_as_uint(vr0[j * 8 + g]);
                uint32_t b1 = __float_as_uint(vr1[j * 8 + g]);
                MMA_TF32(o[j], a0, a1, a2, a3, b0, b1);
            }
        }
    }

    // Normalize, round to tf32 (consumed by out-GEMM), write z
    {
        const float inv0 = 1.0f / l0, inv1 = 1.0f / l1;
        float* zr0 = z + ((size_t)b * CS + q0 + w * 16 + g) * CD + h * CHD;
        float* zr1 = zr0 + 8 * CD;
#pragma unroll
        for (int j = 0; j < 8; j++) {
            float2 v0 = make_float2(tf32r(o[j][0] * inv0), tf32r(o[j][1] * inv0));
            float2 v1 = make_float2(tf32r(o[j][2] * inv1), tf32r(o[j][3] * inv1));
            *(float2*)(zr0 + j * 8 + t * 2) = v0;
            *(float2*)(zr1 + j * 8 + t * 2) = v1;
        }
    }
}

// ---------------------------------------------------------------------------
// Launch
// ---------------------------------------------------------------------------
extern "C" void kernel_launch(void* const* d_in, const int* in_sizes, int n_in,
                              void* d_out, int out_size)
{
    (void)in_sizes; (void)n_in; (void)out_size;
    const float* x     = (const float*)d_in[0];
    const float* mask  = (const float*)d_in[1];
    const float* wq    = (const float*)d_in[2];
    const float* bq    = (const float*)d_in[3];
    const float* w_ckv = (const float*)d_in[4];
    const float* wuk   = (const float*)d_in[5];
    const float* wuv   = (const float*)d_in[6];
    const float* wo    = (const float*)d_in[7];
    const float* bo    = (const float*)d_in[8];
    float* out = (float*)d_out;

    float *pWcat, *pbcat, *pqc, *pv, *pz, *pxr, *pwuvr, *pwor, *ppart;
    cudaGetSymbolAddress((void**)&pWcat,  g_Wcat);
    cudaGetSymbolAddress((void**)&pbcat,  g_bcat);
    cudaGetSymbolAddress((void**)&pqc,    g_qc);
    cudaGetSymbolAddress((void**)&pv,     g_v);
    cudaGetSymbolAddress((void**)&pz,     g_z);
    cudaGetSymbolAddress((void**)&pxr,    g_xr);
    cudaGetSymbolAddress((void**)&pwuvr,  g_wuvr);
    cudaGetSymbolAddress((void**)&pwor,   g_wor);
    cudaGetSymbolAddress((void**)&ppart,  g_part);

    cudaFuncSetAttribute(gemm_rr_async,
                         cudaFuncAttributeMaxDynamicSharedMemorySize, GEMM_SMEM_BYTES);
    cudaFuncSetAttribute(attn_kernel,
                         cudaFuncAttributeMaxDynamicSharedMemorySize, ATT_SMEM_BYTES);

    // 0. tf32-rounded copies of GEMM operands
    round_copy_kernel<<<(MROWS * CD / 4 + 255) / 256, 256>>>(x,   pxr,   MROWS * CD / 4);
    round_copy_kernel<<<(CL * CD / 4 + 255) / 256, 256>>>(wuv, pwuvr, CL * CD / 4);
    round_copy_kernel<<<(CD * CD / 4 + 255) / 256, 256>>>(wo,  pwor,  CD * CD / 4);
    // 1. Wcat[:, 0:512] = rna(wq @ wuk^T) via split-K partials + reduce
    gemm_rt_splitk<<<dim3(CL / 128, CD / 128, NSPLIT), 256>>>(wq, wuk, ppart, CD);
    reduce_compose_kernel<<<CD * CL / 4 / 256, 256>>>(ppart, pWcat);
    // 2. Wcat[:, 512:1024] = rna(w_ckv) ; bcat = [bq @ wuk^T | 0]
    copy_wckv_kernel<<<512, 256>>>(w_ckv, pWcat);
    bcat_kernel<<<CD / 4, 128>>>(bq, wuk, pbcat);
    // 3. qc = rna(x @ Wcat + bcat)   (8192x1024, K=1024) -> [q_latent | combined]
    gemm_rr_async<<<dim3(CD / 128, MROWS / 128), 256, GEMM_SMEM_BYTES>>>(
        pxr, pWcat, pbcat, pqc, CD, CD, CD, CD, 1);
    // 4. v = rna(combined @ wuv)     (8192x1024, K=512)
    gemm_rr_async<<<dim3(CD / 128, MROWS / 128), 256, GEMM_SMEM_BYTES>>>(
        pqc + CL, pwuvr, nullptr, pv, CL, CD, CD, CD, 1);
    // 5. attention -> z (tf32-rounded)
    attn_kernel<<<dim3(CS / 64, CH, CB), 128, ATT_SMEM_BYTES>>>(pqc, pv, mask, pz);
    // 6. out = z @ wo + bo           (8192x1024, K=1024, fp32 out)
    gemm_rr_async<<<dim3(CD / 128, MROWS / 128), 256, GEMM_SMEM_BYTES>>>(
        pz, pwor, bo, out, CD, CD, CD, CD, 0);
}